// round 2
// baseline (speedup 1.0000x reference)
#include <cuda_runtime.h>
#include <cuda_bf16.h>
#include <math.h>

#define D_MODEL 1024
#define D_STATE 16
#define D_CONV 4
#define D_INNER 2048
#define DT_RANK 64
#define BB 2
#define TT 2048
#define NTOK (BB * TT)          // 4096
#define XDBL_W (DT_RANK + 2 * D_STATE)   // 96

// ---------------- scratch (no allocs allowed) ----------------
__device__ float g_xz[(size_t)NTOK * 2 * D_INNER];   // 64MB: [xi | z]
__device__ float g_xc[(size_t)NTOK * D_INNER];       // 32MB
__device__ float g_xdbl[(size_t)NTOK * XDBL_W];
__device__ float g_delta[(size_t)NTOK * D_INNER];    // 32MB (post-softplus)
__device__ float g_gated[(size_t)NTOK * D_INNER];    // 32MB

// ---------------- generic SGEMM: C[M,N] = A[M,K] @ B[K,N] ----------------
// epilogue mode: 0 = none, 1 = softplus(acc + bias[n])
#define BM 128
#define BN 128
#define BK 8
#define TM 8
#define TN 8

__global__ __launch_bounds__(256) void sgemm_k(
    const float* __restrict__ A, const float* __restrict__ B, float* __restrict__ C,
    int M, int N, int K, int lda, int ldb, int ldc,
    const float* __restrict__ bias, int mode)
{
    __shared__ float As[BK][BM];
    __shared__ float Bs[BK][BN];
    const int tid = threadIdx.x;
    const int brow = blockIdx.y * BM;
    const int bcol = blockIdx.x * BN;
    const int tx = tid % (BN / TN);   // 16
    const int ty = tid / (BN / TN);   // 16

    float acc[TM][TN];
#pragma unroll
    for (int i = 0; i < TM; i++)
#pragma unroll
        for (int j = 0; j < TN; j++) acc[i][j] = 0.f;

    for (int k0 = 0; k0 < K; k0 += BK) {
        // load A tile (BM x BK) as float4
        {
            int m = tid >> 1;              // 0..127
            int k4 = (tid & 1) * 4;        // 0 or 4
            int gm = brow + m;
            float4 v = make_float4(0.f, 0.f, 0.f, 0.f);
            if (gm < M)
                v = *(const float4*)&A[(size_t)gm * lda + k0 + k4];
            As[k4 + 0][m] = v.x;
            As[k4 + 1][m] = v.y;
            As[k4 + 2][m] = v.z;
            As[k4 + 3][m] = v.w;
        }
        // load B tile (BK x BN)
        {
            int kk = tid >> 5;             // 0..7
            int n4 = (tid & 31) * 4;       // 0..124
            int gn = bcol + n4;
            const float* bp = &B[(size_t)(k0 + kk) * ldb + gn];
            float4 v;
            if (gn + 3 < N) {
                v = *(const float4*)bp;
            } else {
                v.x = (gn + 0 < N) ? bp[0] : 0.f;
                v.y = (gn + 1 < N) ? bp[1] : 0.f;
                v.z = (gn + 2 < N) ? bp[2] : 0.f;
                v.w = (gn + 3 < N) ? bp[3] : 0.f;
            }
            Bs[kk][n4 + 0] = v.x;
            Bs[kk][n4 + 1] = v.y;
            Bs[kk][n4 + 2] = v.z;
            Bs[kk][n4 + 3] = v.w;
        }
        __syncthreads();

#pragma unroll
        for (int kk = 0; kk < BK; kk++) {
            float ar[TM], br[TN];
#pragma unroll
            for (int i = 0; i < TM; i++) ar[i] = As[kk][ty * TM + i];
#pragma unroll
            for (int j = 0; j < TN; j++) br[j] = Bs[kk][tx * TN + j];
#pragma unroll
            for (int i = 0; i < TM; i++)
#pragma unroll
                for (int j = 0; j < TN; j++) acc[i][j] += ar[i] * br[j];
        }
        __syncthreads();
    }

#pragma unroll
    for (int i = 0; i < TM; i++) {
        int gm = brow + ty * TM + i;
        if (gm >= M) continue;
#pragma unroll
        for (int j = 0; j < TN; j++) {
            int gn = bcol + tx * TN + j;
            if (gn >= N) continue;
            float v = acc[i][j];
            if (mode == 1) {
                v += bias[gn];
                // stable softplus
                v = fmaxf(v, 0.f) + log1pf(__expf(-fabsf(v)));
            }
            C[(size_t)gm * ldc + gn] = v;
        }
    }
}

// ---------------- causal depthwise conv + silu ----------------
__global__ void conv_silu_k(const float* __restrict__ conv_w,
                            const float* __restrict__ conv_b)
{
    int idx = blockIdx.x * blockDim.x + threadIdx.x;
    if (idx >= NTOK * D_INNER) return;
    int d = idx % D_INNER;
    int bt = idx / D_INNER;
    int t = bt % TT;
    int b = bt / TT;

    float w0 = conv_w[d * D_CONV + 0];
    float w1 = conv_w[d * D_CONV + 1];
    float w2 = conv_w[d * D_CONV + 2];
    float w3 = conv_w[d * D_CONV + 3];

    size_t base = ((size_t)b * TT) * (2 * D_INNER) + d;
    float s = conv_b[d];
    if (t - 3 >= 0) s += w0 * g_xz[base + (size_t)(t - 3) * (2 * D_INNER)];
    if (t - 2 >= 0) s += w1 * g_xz[base + (size_t)(t - 2) * (2 * D_INNER)];
    if (t - 1 >= 0) s += w2 * g_xz[base + (size_t)(t - 1) * (2 * D_INNER)];
    s += w3 * g_xz[base + (size_t)t * (2 * D_INNER)];

    float sig = 1.f / (1.f + __expf(-s));
    g_xc[idx] = s * sig;
}

// ---------------- fused selective scan + skip + gate (software-pipelined) ----
// 4 threads per (b,d) channel, 4 states each. 128 threads/block -> 32 channels.
__global__ __launch_bounds__(128) void scan_k(const float* __restrict__ A_log,
                                              const float* __restrict__ Dp)
{
    const int tid = threadIdx.x;
    const int sub = tid & 3;                       // 4-state slice
    const int ch = blockIdx.x * 32 + (tid >> 2);   // channel 0..4095
    const int b = ch >> 11;
    const int d = ch & 2047;

    float A_neg[4];
#pragma unroll
    for (int i = 0; i < 4; i++)
        A_neg[i] = -__expf(A_log[d * D_STATE + sub * 4 + i]);

    const float Dd = Dp[d];
    float h[4] = {0.f, 0.f, 0.f, 0.f};

    const size_t row = (size_t)b * TT;

    // prefetch t = 0
    size_t tok0 = row;
    size_t idx0 = tok0 * D_INNER + d;
    float dlt = g_delta[idx0];
    float u   = g_xc[idx0];
    float z   = g_xz[tok0 * (2 * D_INNER) + D_INNER + d];
    const float* xd0 = &g_xdbl[tok0 * XDBL_W];
    float4 Bv = *(const float4*)&xd0[DT_RANK + sub * 4];
    float4 Cv = *(const float4*)&xd0[DT_RANK + D_STATE + sub * 4];

    for (int t = 0; t < TT; t++) {
        // issue prefetch for t+1 before compute (hide memory latency)
        float dlt_n = 0.f, u_n = 0.f, z_n = 0.f;
        float4 Bv_n = make_float4(0, 0, 0, 0), Cv_n = Bv_n;
        if (t + 1 < TT) {
            size_t tok = row + t + 1;
            size_t idx = tok * D_INNER + d;
            dlt_n = g_delta[idx];
            u_n   = g_xc[idx];
            z_n   = g_xz[tok * (2 * D_INNER) + D_INNER + d];
            const float* xd = &g_xdbl[tok * XDBL_W];
            Bv_n = *(const float4*)&xd[DT_RANK + sub * 4];
            Cv_n = *(const float4*)&xd[DT_RANK + D_STATE + sub * 4];
        }

        // compute step t
        float du = dlt * u;
        float Bn[4] = {Bv.x, Bv.y, Bv.z, Bv.w};
        float Cn[4] = {Cv.x, Cv.y, Cv.z, Cv.w};
        float yp = 0.f;
#pragma unroll
        for (int i = 0; i < 4; i++) {
            float dA = __expf(dlt * A_neg[i]);
            h[i] = dA * h[i] + du * Bn[i];
            yp += h[i] * Cn[i];
        }
        yp += __shfl_xor_sync(0xffffffffu, yp, 1);
        yp += __shfl_xor_sync(0xffffffffu, yp, 2);

        if (sub == 0) {
            float y = yp + u * Dd;
            float sig = 1.f / (1.f + __expf(-z));
            g_gated[(row + t) * D_INNER + d] = y * (z * sig);
        }

        dlt = dlt_n; u = u_n; z = z_n; Bv = Bv_n; Cv = Cv_n;
    }
}

// ---------------- launch ----------------
extern "C" void kernel_launch(void* const* d_in, const int* in_sizes, int n_in,
                              void* d_out, int out_size)
{
    const float* x      = (const float*)d_in[0];
    const float* W_in   = (const float*)d_in[1];
    const float* conv_w = (const float*)d_in[2];
    const float* conv_b = (const float*)d_in[3];
    const float* W_x    = (const float*)d_in[4];
    const float* W_dt   = (const float*)d_in[5];
    const float* b_dt   = (const float*)d_in[6];
    const float* A_log  = (const float*)d_in[7];
    const float* Dp     = (const float*)d_in[8];
    const float* W_out  = (const float*)d_in[9];
    float* out = (float*)d_out;

    float *xz, *xc, *xdbl, *delta, *gated;
    cudaGetSymbolAddress((void**)&xz, g_xz);
    cudaGetSymbolAddress((void**)&xc, g_xc);
    cudaGetSymbolAddress((void**)&xdbl, g_xdbl);
    cudaGetSymbolAddress((void**)&delta, g_delta);
    cudaGetSymbolAddress((void**)&gated, g_gated);

    // 1) xz = x @ W_in : (4096,1024)@(1024,4096)
    sgemm_k<<<dim3((2 * D_INNER + BN - 1) / BN, (NTOK + BM - 1) / BM), 256>>>(
        x, W_in, xz, NTOK, 2 * D_INNER, D_MODEL, D_MODEL, 2 * D_INNER, 2 * D_INNER,
        nullptr, 0);

    // 2) causal depthwise conv + silu -> xc
    {
        int n = NTOK * D_INNER;
        conv_silu_k<<<(n + 255) / 256, 256>>>(conv_w, conv_b);
    }

    // 3) x_dbl = xc @ W_x : (4096,2048)@(2048,96)
    sgemm_k<<<dim3((XDBL_W + BN - 1) / BN, (NTOK + BM - 1) / BM), 256>>>(
        xc, W_x, xdbl, NTOK, XDBL_W, D_INNER, D_INNER, XDBL_W, XDBL_W,
        nullptr, 0);

    // 4) delta = softplus(x_dbl[:, :64] @ W_dt + b_dt)   (lda=96 slices dt)
    sgemm_k<<<dim3((D_INNER + BN - 1) / BN, (NTOK + BM - 1) / BM), 256>>>(
        xdbl, W_dt, delta, NTOK, D_INNER, DT_RANK, XDBL_W, D_INNER, D_INNER,
        b_dt, 1);

    // 5) selective scan + skip + gate -> gated
    scan_k<<<128, 128>>>(A_log, Dp);

    // 6) out = gated @ W_out : (4096,2048)@(2048,1024)
    sgemm_k<<<dim3((D_MODEL + BN - 1) / BN, (NTOK + BM - 1) / BM), 256>>>(
        gated, W_out, out, NTOK, D_MODEL, D_INNER, D_INNER, D_MODEL, D_MODEL,
        nullptr, 0);
}

// round 13
// speedup vs baseline: 1.2934x; 1.2934x over previous
#include <cuda_runtime.h>
#include <cuda_bf16.h>
#include <math.h>
#include <stdint.h>

#define D_MODEL 1024
#define D_STATE 16
#define D_CONV 4
#define D_INNER 2048
#define DT_RANK 64
#define BB 2
#define TT 2048
#define NTOK (BB * TT)          // 4096
#define XDBL_W (DT_RANK + 2 * D_STATE)   // 96

// ---------------- scratch (no allocs allowed) ----------------
__device__ float g_xz[(size_t)NTOK * 2 * D_INNER];   // [xi | z]
__device__ float g_xc[(size_t)NTOK * D_INNER];
__device__ float g_xdbl[(size_t)NTOK * XDBL_W];
__device__ float g_delta[(size_t)NTOK * D_INNER];    // post-softplus
__device__ float g_gated[(size_t)NTOK * D_INNER];

// ================= 3xTF32 tensor-core GEMM =================
// C[M,N] = A[M,K] @ B[K,N], row-major, strides lda/ldb/ldc.
// CTA tile 128x128x16, 8 warps (2x4), warp tile 64x32, mma.m16n8k8.tf32.
// Precision: split each operand v = hi + lo (RN tf32), accumulate
// hi*hi + hi*lo + lo*hi  -> ~fp32 accuracy at 3x MMA cost.
// mode: 0 = none, 1 = softplus(acc + bias[n])
#define GBM 128
#define GBN 128
#define GBK 16
#define A_PAD 20    // GBK + 4
#define B_PAD 136   // GBN + 8

__device__ __forceinline__ void cp_async16(uint32_t dst, const void* src) {
    asm volatile("cp.async.cg.shared.global [%0], [%1], 16;" :: "r"(dst), "l"(src));
}
__device__ __forceinline__ void cp_async16z(uint32_t dst, const void* src, int sz) {
    asm volatile("cp.async.cg.shared.global [%0], [%1], 16, %2;" :: "r"(dst), "l"(src), "r"(sz));
}

__device__ __forceinline__ uint32_t f2tf32(float x) {
    uint32_t r;
    asm("cvt.rna.tf32.f32 %0, %1;" : "=r"(r) : "f"(x));
    return r;
}
// split v into hi (tf32, RN) and lo (tf32 of residual)
__device__ __forceinline__ void tf32_split(float v, uint32_t& hi, uint32_t& lo) {
    hi = f2tf32(v);
    lo = f2tf32(v - __uint_as_float(hi));
}

__device__ __forceinline__ void mma_tf32(float c[4],
    const uint32_t a[4], const uint32_t b[2])
{
    asm volatile(
        "mma.sync.aligned.m16n8k8.row.col.f32.tf32.tf32.f32 "
        "{%0,%1,%2,%3}, {%4,%5,%6,%7}, {%8,%9}, {%0,%1,%2,%3};\n"
        : "+f"(c[0]), "+f"(c[1]), "+f"(c[2]), "+f"(c[3])
        : "r"(a[0]), "r"(a[1]), "r"(a[2]), "r"(a[3]), "r"(b[0]), "r"(b[1]));
}

__global__ __launch_bounds__(256) void tf32gemm_k(
    const float* __restrict__ A, const float* __restrict__ B, float* __restrict__ C,
    int M, int N, int K, int lda, int ldb, int ldc,
    const float* __restrict__ bias, int mode)
{
    __shared__ float As[2][GBM][A_PAD];   // [stage][m][k]
    __shared__ float Bs[2][GBK][B_PAD];   // [stage][k][n]

    const int tid = threadIdx.x;
    const int wid = tid >> 5;
    const int lane = tid & 31;
    const int g = lane >> 2;     // groupID 0..7
    const int cI = lane & 3;     // ctid 0..3
    const int wm = wid >> 2;     // 0..1
    const int wn = wid & 3;      // 0..3
    const int brow = blockIdx.y * GBM;
    const int bcol = blockIdx.x * GBN;

    uint32_t as_base = (uint32_t)__cvta_generic_to_shared(&As[0][0][0]);
    uint32_t bs_base = (uint32_t)__cvta_generic_to_shared(&Bs[0][0][0]);
    const uint32_t as_stage = GBM * A_PAD * 4;
    const uint32_t bs_stage = GBK * B_PAD * 4;

    float acc[4][4][4];
#pragma unroll
    for (int i = 0; i < 4; i++)
#pragma unroll
        for (int j = 0; j < 4; j++)
#pragma unroll
            for (int r = 0; r < 4; r++) acc[i][j][r] = 0.f;

    const int KT = K / GBK;

    // ---- issue loads for a tile into stage s ----
    auto issue_tile = [&](int kt, int s) {
        int k0 = kt * GBK;
        // A: 128 rows x 16 floats = 512 16B-chunks
        const float* Ab = A + (size_t)brow * lda + k0;
#pragma unroll
        for (int i = 0; i < 2; i++) {
            int ch = tid + i * 256;
            int m = ch >> 2;
            int ko = (ch & 3) * 4;
            uint32_t dst = as_base + s * as_stage + (uint32_t)(m * A_PAD + ko) * 4;
            cp_async16(dst, Ab + (size_t)m * lda + ko);
        }
        // B: 16 rows x 128 floats = 512 chunks
        const float* Bb = B + (size_t)k0 * ldb + bcol;
#pragma unroll
        for (int i = 0; i < 2; i++) {
            int ch = tid + i * 256;
            int kk = ch >> 5;
            int n4 = (ch & 31) * 4;
            uint32_t dst = bs_base + s * bs_stage + (uint32_t)(kk * B_PAD + n4) * 4;
            int sz = (bcol + n4 + 4 <= N) ? 16 : 0;
            cp_async16z(dst, Bb + (size_t)kk * ldb + n4, sz);
        }
        asm volatile("cp.async.commit_group;");
    };

    issue_tile(0, 0);

    for (int kt = 0; kt < KT; kt++) {
        int s = kt & 1;
        if (kt + 1 < KT) {
            issue_tile(kt + 1, (kt + 1) & 1);
            asm volatile("cp.async.wait_group 1;");
        } else {
            asm volatile("cp.async.wait_group 0;");
        }
        __syncthreads();

#pragma unroll
        for (int kk = 0; kk < GBK; kk += 8) {
            uint32_t afh[4][4], afl[4][4];
#pragma unroll
            for (int mi = 0; mi < 4; mi++) {
                int m = wm * 64 + mi * 16 + g;
                tf32_split(As[s][m][kk + cI],         afh[mi][0], afl[mi][0]);
                tf32_split(As[s][m + 8][kk + cI],     afh[mi][1], afl[mi][1]);
                tf32_split(As[s][m][kk + cI + 4],     afh[mi][2], afl[mi][2]);
                tf32_split(As[s][m + 8][kk + cI + 4], afh[mi][3], afl[mi][3]);
            }
            uint32_t bfh[4][2], bfl[4][2];
#pragma unroll
            for (int ni = 0; ni < 4; ni++) {
                int n = wn * 32 + ni * 8 + g;
                tf32_split(Bs[s][kk + cI][n],     bfh[ni][0], bfl[ni][0]);
                tf32_split(Bs[s][kk + cI + 4][n], bfh[ni][1], bfl[ni][1]);
            }
#pragma unroll
            for (int mi = 0; mi < 4; mi++)
#pragma unroll
                for (int ni = 0; ni < 4; ni++) {
                    mma_tf32(acc[mi][ni], afh[mi], bfh[ni]);  // hi*hi
                    mma_tf32(acc[mi][ni], afl[mi], bfh[ni]);  // lo*hi
                    mma_tf32(acc[mi][ni], afh[mi], bfl[ni]);  // hi*lo
                }
        }
        __syncthreads();
    }

    // ---- epilogue + store ----
#pragma unroll
    for (int mi = 0; mi < 4; mi++) {
        int gm0 = brow + wm * 64 + mi * 16 + g;
#pragma unroll
        for (int ni = 0; ni < 4; ni++) {
            int gn = bcol + wn * 32 + ni * 8 + cI * 2;
#pragma unroll
            for (int r = 0; r < 4; r++) {
                int gm = gm0 + (r >= 2 ? 8 : 0);
                int gcol = gn + (r & 1);
                if (gcol >= N) continue;
                float v = acc[mi][ni][r];
                if (mode == 1) {
                    v += bias[gcol];
                    v = fmaxf(v, 0.f) + log1pf(__expf(-fabsf(v)));
                }
                C[(size_t)gm * ldc + gcol] = v;
            }
        }
    }
}

// ---------------- causal depthwise conv + silu ----------------
__global__ void conv_silu_k(const float* __restrict__ conv_w,
                            const float* __restrict__ conv_b)
{
    int idx = blockIdx.x * blockDim.x + threadIdx.x;
    if (idx >= NTOK * D_INNER) return;
    int d = idx % D_INNER;
    int bt = idx / D_INNER;
    int t = bt % TT;
    int b = bt / TT;

    float w0 = conv_w[d * D_CONV + 0];
    float w1 = conv_w[d * D_CONV + 1];
    float w2 = conv_w[d * D_CONV + 2];
    float w3 = conv_w[d * D_CONV + 3];

    size_t base = ((size_t)b * TT) * (2 * D_INNER) + d;
    float s = conv_b[d];
    if (t - 3 >= 0) s += w0 * g_xz[base + (size_t)(t - 3) * (2 * D_INNER)];
    if (t - 2 >= 0) s += w1 * g_xz[base + (size_t)(t - 2) * (2 * D_INNER)];
    if (t - 1 >= 0) s += w2 * g_xz[base + (size_t)(t - 1) * (2 * D_INNER)];
    s += w3 * g_xz[base + (size_t)t * (2 * D_INNER)];

    float sig = 1.f / (1.f + __expf(-s));
    g_xc[idx] = s * sig;
}

// ---------------- fused selective scan + skip + gate (pipelined) ----------
__global__ __launch_bounds__(128) void scan_k(const float* __restrict__ A_log,
                                              const float* __restrict__ Dp)
{
    const int tid = threadIdx.x;
    const int sub = tid & 3;
    const int ch = blockIdx.x * 32 + (tid >> 2);
    const int b = ch >> 11;
    const int d = ch & 2047;

    float A_neg[4];
#pragma unroll
    for (int i = 0; i < 4; i++)
        A_neg[i] = -__expf(A_log[d * D_STATE + sub * 4 + i]);

    const float Dd = Dp[d];
    float h[4] = {0.f, 0.f, 0.f, 0.f};
    const size_t row = (size_t)b * TT;

    size_t tok0 = row;
    size_t idx0 = tok0 * D_INNER + d;
    float dlt = g_delta[idx0];
    float u   = g_xc[idx0];
    float z   = g_xz[tok0 * (2 * D_INNER) + D_INNER + d];
    const float* xd0 = &g_xdbl[tok0 * XDBL_W];
    float4 Bv = *(const float4*)&xd0[DT_RANK + sub * 4];
    float4 Cv = *(const float4*)&xd0[DT_RANK + D_STATE + sub * 4];

    for (int t = 0; t < TT; t++) {
        float dlt_n = 0.f, u_n = 0.f, z_n = 0.f;
        float4 Bv_n = make_float4(0, 0, 0, 0), Cv_n = Bv_n;
        if (t + 1 < TT) {
            size_t tok = row + t + 1;
            size_t idx = tok * D_INNER + d;
            dlt_n = g_delta[idx];
            u_n   = g_xc[idx];
            z_n   = g_xz[tok * (2 * D_INNER) + D_INNER + d];
            const float* xd = &g_xdbl[tok * XDBL_W];
            Bv_n = *(const float4*)&xd[DT_RANK + sub * 4];
            Cv_n = *(const float4*)&xd[DT_RANK + D_STATE + sub * 4];
        }

        float du = dlt * u;
        float Bn[4] = {Bv.x, Bv.y, Bv.z, Bv.w};
        float Cn[4] = {Cv.x, Cv.y, Cv.z, Cv.w};
        float yp = 0.f;
#pragma unroll
        for (int i = 0; i < 4; i++) {
            float dA = __expf(dlt * A_neg[i]);
            h[i] = dA * h[i] + du * Bn[i];
            yp += h[i] * Cn[i];
        }
        yp += __shfl_xor_sync(0xffffffffu, yp, 1);
        yp += __shfl_xor_sync(0xffffffffu, yp, 2);

        if (sub == 0) {
            float y = yp + u * Dd;
            float sig = 1.f / (1.f + __expf(-z));
            g_gated[(row + t) * D_INNER + d] = y * (z * sig);
        }

        dlt = dlt_n; u = u_n; z = z_n; Bv = Bv_n; Cv = Cv_n;
    }
}

// ---------------- launch ----------------
extern "C" void kernel_launch(void* const* d_in, const int* in_sizes, int n_in,
                              void* d_out, int out_size)
{
    const float* x      = (const float*)d_in[0];
    const float* W_in   = (const float*)d_in[1];
    const float* conv_w = (const float*)d_in[2];
    const float* conv_b = (const float*)d_in[3];
    const float* W_x    = (const float*)d_in[4];
    const float* W_dt   = (const float*)d_in[5];
    const float* b_dt   = (const float*)d_in[6];
    const float* A_log  = (const float*)d_in[7];
    const float* Dp     = (const float*)d_in[8];
    const float* W_out  = (const float*)d_in[9];
    float* out = (float*)d_out;

    float *xz, *xc, *xdbl, *delta, *gated;
    cudaGetSymbolAddress((void**)&xz, g_xz);
    cudaGetSymbolAddress((void**)&xc, g_xc);
    cudaGetSymbolAddress((void**)&xdbl, g_xdbl);
    cudaGetSymbolAddress((void**)&delta, g_delta);
    cudaGetSymbolAddress((void**)&gated, g_gated);

    // 1) xz = x @ W_in : (4096,1024)@(1024,4096)
    tf32gemm_k<<<dim3(2 * D_INNER / GBN, NTOK / GBM), 256>>>(
        x, W_in, xz, NTOK, 2 * D_INNER, D_MODEL, D_MODEL, 2 * D_INNER, 2 * D_INNER,
        nullptr, 0);

    // 2) causal depthwise conv + silu -> xc
    {
        int n = NTOK * D_INNER;
        conv_silu_k<<<(n + 255) / 256, 256>>>(conv_w, conv_b);
    }

    // 3) x_dbl = xc @ W_x : (4096,2048)@(2048,96)
    tf32gemm_k<<<dim3((XDBL_W + GBN - 1) / GBN, NTOK / GBM), 256>>>(
        xc, W_x, xdbl, NTOK, XDBL_W, D_INNER, D_INNER, XDBL_W, XDBL_W,
        nullptr, 0);

    // 4) delta = softplus(x_dbl[:, :64] @ W_dt + b_dt)   (lda=96 slices dt)
    tf32gemm_k<<<dim3(D_INNER / GBN, NTOK / GBM), 256>>>(
        xdbl, W_dt, delta, NTOK, D_INNER, DT_RANK, XDBL_W, D_INNER, D_INNER,
        b_dt, 1);

    // 5) selective scan + skip + gate -> gated
    scan_k<<<128, 128>>>(A_log, Dp);

    // 6) out = gated @ W_out : (4096,2048)@(2048,1024)
    tf32gemm_k<<<dim3(D_MODEL / GBN, NTOK / GBM), 256>>>(
        gated, W_out, out, NTOK, D_MODEL, D_INNER, D_INNER, D_MODEL, D_MODEL,
        nullptr, 0);
}